// round 1
// baseline (speedup 1.0000x reference)
#include <cuda_runtime.h>
#include <math.h>

#define B   128
#define T_  400
#define KV  128
#define V_  1024
#define E_  256
#define H_  512
#define L_  300
#define NEG (-1e9f)

// ---------------- persistent device state ----------------
__device__ float g_h1a[B * H_];
__device__ float g_h1b[B * H_];
__device__ float g_c1 [B * H_];
__device__ float g_h2 [B * KV];
__device__ float g_c2 [B * KV];
__device__ float g_ctx[B * KV];

__device__ __forceinline__ float sigm(float x) { return 1.0f / (1.0f + expf(-x)); }

// ---------------- init: zero recurrent state ----------------
__global__ __launch_bounds__(256) void k_init() {
    int stride = gridDim.x * blockDim.x;
    int i0 = blockIdx.x * blockDim.x + threadIdx.x;
    for (int i = i0; i < B * H_; i += stride) { g_h1a[i] = 0.f; g_h1b[i] = 0.f; g_c1[i] = 0.f; }
    for (int i = i0; i < B * KV; i += stride) { g_h2[i] = 0.f; g_c2[i] = 0.f; g_ctx[i] = 0.f; }
}

// ---------------- logits block (shared by fused + final kernel) ----------------
// c2 in [0,64): 8 v-tiles(128) x 8 b-tiles(16). K = 256 ([h2, ctx]).
__device__ void logits_block(int c2, const float* __restrict__ w_out,
                             const float* __restrict__ b_out,
                             float* __restrict__ out, int tout) {
    __shared__ float as_[16 * 256];
    const int tid = threadIdx.x;
    const int vt = c2 & 7, bt = c2 >> 3;
    const int v0 = vt * 128, b0 = bt * 16;

    for (int e = tid; e < 16 * 256; e += 256) {
        int bb = e >> 8, kk = e & 255;
        float v = (kk < 128) ? g_h2[(b0 + bb) * KV + kk]
                             : g_ctx[(b0 + bb) * KV + (kk - 128)];
        as_[e] = v;
    }
    __syncthreads();

    const int vl = tid & 127, bg = tid >> 7;       // 128 v-lanes x 2 b-groups(8)
    float acc[8];
#pragma unroll
    for (int r = 0; r < 8; r++) acc[r] = 0.f;
    const float* wr = w_out + (size_t)(v0 + vl) * 256;
#pragma unroll 4
    for (int kk = 0; kk < 256; kk++) {
        float w = wr[kk];
#pragma unroll
        for (int r = 0; r < 8; r++) acc[r] += w * as_[(bg * 8 + r) * 256 + kk];
    }
    const float bo = b_out[v0 + vl];
#pragma unroll
    for (int r = 0; r < 8; r++) {
        int b = b0 + bg * 8 + r;
        out[((size_t)b * L_ + tout) * V_ + (v0 + vl)] = acc[r] + bo;
    }
}

// ---------------- kernel 1: LSTM1(t) on CTAs [0,128) + logits(t-1) on CTAs [128,192) ----
__global__ __launch_bounds__(256) void k_step1(
    const float* __restrict__ emb, const int* __restrict__ y,
    const float* __restrict__ w_ih1, const float* __restrict__ w_hh1,
    const float* __restrict__ b_ih1, const float* __restrict__ b_hh1,
    const float* __restrict__ w_out, const float* __restrict__ b_out,
    float* __restrict__ out, int t)
{
    const int c = blockIdx.x;
    if (c >= 128) {
        if (t > 0) logits_block(c - 128, w_out, b_out, out, t - 1);
        return;
    }
    // LSTM1: CTA = 16 b x 32 h-units (4 gates each). 8 btiles x 16 htiles.
    __shared__ float xs[16 * 33];     // act tile  [b][k], pitch 33
    __shared__ float ws[128 * 33];    // weight tile [4g*32h][k], pitch 33
    __shared__ int   toks_s[16];

    const int tid = threadIdx.x;
    const int btile = c & 7, htile = c >> 3;
    const int b0 = btile * 16, h0 = htile * 32;
    const float* __restrict__ h1r = (t & 1) ? g_h1b : g_h1a;   // read: prev
    float* __restrict__       h1w = (t & 1) ? g_h1a : g_h1b;   // write: new

    if (tid < 16)
        toks_s[tid] = (t == 0) ? 1 : y[(b0 + tid) * L_ + (t - 1)];
    __syncthreads();

    float acc0[4] = {0.f, 0.f, 0.f, 0.f};
    float acc1[4] = {0.f, 0.f, 0.f, 0.f};
    const int hl = tid & 31, bg = tid >> 5;    // 32 h-lanes x 8 b-groups(2)
    const int bA = bg * 2, bB = bA + 1;

    // ---- segment 1: x = [emb(256), ctx(128)],  K = 384, weights w_ih1 ----
    for (int kbase = 0; kbase < 384; kbase += 32) {
        for (int e = tid; e < 512; e += 256) {
            int bb = e >> 5, kk = e & 31;
            int k = kbase + kk;
            float v;
            if (k < 256) v = emb[(size_t)toks_s[bb] * E_ + k];
            else         v = g_ctx[(b0 + bb) * KV + (k - 256)];
            xs[bb * 33 + kk] = v;
        }
        for (int e = tid; e < 4096; e += 256) {
            int row = e >> 5, kk = e & 31;
            int g = row >> 5, hh = row & 31;
            ws[row * 33 + kk] = w_ih1[(size_t)(g * H_ + h0 + hh) * 384 + kbase + kk];
        }
        __syncthreads();
#pragma unroll
        for (int kk = 0; kk < 32; kk++) {
            float a0 = xs[bA * 33 + kk];
            float a1 = xs[bB * 33 + kk];
#pragma unroll
            for (int g = 0; g < 4; g++) {
                float w = ws[((g << 5) + hl) * 33 + kk];
                acc0[g] += w * a0;
                acc1[g] += w * a1;
            }
        }
        __syncthreads();
    }
    // ---- segment 2: h1 (prev), K = 512, weights w_hh1 ----
    for (int kbase = 0; kbase < 512; kbase += 32) {
        for (int e = tid; e < 512; e += 256) {
            int bb = e >> 5, kk = e & 31;
            xs[bb * 33 + kk] = h1r[(size_t)(b0 + bb) * H_ + kbase + kk];
        }
        for (int e = tid; e < 4096; e += 256) {
            int row = e >> 5, kk = e & 31;
            int g = row >> 5, hh = row & 31;
            ws[row * 33 + kk] = w_hh1[(size_t)(g * H_ + h0 + hh) * H_ + kbase + kk];
        }
        __syncthreads();
#pragma unroll
        for (int kk = 0; kk < 32; kk++) {
            float a0 = xs[bA * 33 + kk];
            float a1 = xs[bB * 33 + kk];
#pragma unroll
            for (int g = 0; g < 4; g++) {
                float w = ws[((g << 5) + hl) * 33 + kk];
                acc0[g] += w * a0;
                acc1[g] += w * a1;
            }
        }
        __syncthreads();
    }

    // ---- epilogue: LSTM pointwise ----
    const int hidx = h0 + hl;
    float bias[4];
#pragma unroll
    for (int g = 0; g < 4; g++) bias[g] = b_ih1[g * H_ + hidx] + b_hh1[g * H_ + hidx];

    {
        int b = b0 + bA;
        float gi = acc0[0] + bias[0], gf = acc0[1] + bias[1];
        float gg = acc0[2] + bias[2], go = acc0[3] + bias[3];
        float co = g_c1[(size_t)b * H_ + hidx];
        float cn = sigm(gf) * co + sigm(gi) * tanhf(gg);
        g_c1[(size_t)b * H_ + hidx] = cn;
        h1w[(size_t)b * H_ + hidx]  = sigm(go) * tanhf(cn);
    }
    {
        int b = b0 + bB;
        float gi = acc1[0] + bias[0], gf = acc1[1] + bias[1];
        float gg = acc1[2] + bias[2], go = acc1[3] + bias[3];
        float co = g_c1[(size_t)b * H_ + hidx];
        float cn = sigm(gf) * co + sigm(gi) * tanhf(gg);
        g_c1[(size_t)b * H_ + hidx] = cn;
        h1w[(size_t)b * H_ + hidx]  = sigm(go) * tanhf(cn);
    }
}

// ---------------- kernel 2: LSTM2 (1 CTA per batch row) ----------------
__global__ __launch_bounds__(256) void k_lstm2(
    const float* __restrict__ w_ih2, const float* __restrict__ w_hh2,
    const float* __restrict__ bi2,  const float* __restrict__ bh2, int t)
{
    const int b = blockIdx.x;
    const int tid = threadIdx.x;
    __shared__ float act[640];      // [h1_new(512), h2_old(128)]
    __shared__ float red[512];

    const float* __restrict__ h1n = (t & 1) ? g_h1a : g_h1b;   // NEW h1 (written by k_step1)
    for (int i = tid; i < 512; i += 256) act[i] = h1n[(size_t)b * H_ + i];
    if (tid < 128) act[512 + tid] = g_h2[b * KV + tid];
    __syncthreads();

    const int hl = tid & 127, kh = tid >> 7;   // 128 h-units x 2 K-halves(320)
    float acc[4] = {0.f, 0.f, 0.f, 0.f};
    const int k0 = kh * 320, k1 = k0 + 320;
    const int e1 = (k1 < 512) ? k1 : 512;
#pragma unroll 4
    for (int k = k0; k < e1; k++) {
        float a = act[k];
#pragma unroll
        for (int g = 0; g < 4; g++) acc[g] += w_ih2[(size_t)(g * KV + hl) * H_ + k] * a;
    }
    const int s0 = (k0 > 512) ? k0 : 512;
#pragma unroll 4
    for (int k = s0; k < k1; k++) {
        float a = act[k];
#pragma unroll
        for (int g = 0; g < 4; g++) acc[g] += w_hh2[(size_t)(g * KV + hl) * KV + (k - 512)] * a;
    }
    if (kh == 1) {
#pragma unroll
        for (int g = 0; g < 4; g++) red[g * 128 + hl] = acc[g];
    }
    __syncthreads();
    if (kh == 0) {
        float gt[4];
#pragma unroll
        for (int g = 0; g < 4; g++)
            gt[g] = acc[g] + red[g * 128 + hl] + bi2[g * KV + hl] + bh2[g * KV + hl];
        float co = g_c2[b * KV + hl];
        float cn = sigm(gt[1]) * co + sigm(gt[0]) * tanhf(gt[2]);
        g_c2[b * KV + hl] = cn;
        g_h2[b * KV + hl] = sigm(gt[3]) * tanhf(cn);
    }
}

// ---------------- kernel 3: attention (1 CTA per batch row) ----------------
__global__ __launch_bounds__(256) void k_attn(
    const float* __restrict__ key, const float* __restrict__ val,
    const int* __restrict__ elen, float* __restrict__ out, int t)
{
    const int b = blockIdx.x;
    const int tid = threadIdx.x;
    __shared__ float q[128];
    __shared__ float a[T_];
    __shared__ float red[256];
    __shared__ float cred[128];

    if (tid < 128) q[tid] = g_h2[b * KV + tid];
    __syncthreads();
    const int len = elen[b];

    // energies (masked)
    for (int tt = tid; tt < T_; tt += 256) {
        float s = 0.f;
        if (tt < len) {
            const float4* kr = (const float4*)(key + ((size_t)b * T_ + tt) * KV);
            const float4* qv = (const float4*)q;
#pragma unroll
            for (int i = 0; i < 32; i++) {
                float4 kk = kr[i], qq = qv[i];
                s += kk.x * qq.x + kk.y * qq.y + kk.z * qq.z + kk.w * qq.w;
            }
        } else s = NEG;
        a[tt] = s;
    }
    __syncthreads();

    // max-reduce
    float m = -3.4e38f;
    for (int tt = tid; tt < T_; tt += 256) m = fmaxf(m, a[tt]);
    red[tid] = m; __syncthreads();
    for (int s = 128; s > 0; s >>= 1) {
        if (tid < s) red[tid] = fmaxf(red[tid], red[tid + s]);
        __syncthreads();
    }
    m = red[0]; __syncthreads();

    // exp + sum-reduce
    float sum = 0.f;
    for (int tt = tid; tt < T_; tt += 256) {
        float p = expf(a[tt] - m);
        a[tt] = p; sum += p;
    }
    red[tid] = sum; __syncthreads();
    for (int s = 128; s > 0; s >>= 1) {
        if (tid < s) red[tid] += red[tid + s];
        __syncthreads();
    }
    const float inv = 1.0f / red[0]; __syncthreads();

    // normalize
    for (int tt = tid; tt < T_; tt += 256) a[tt] *= inv;
    __syncthreads();

    // context = attn @ value
    const int k = tid & 127, kh = tid >> 7;
    float acc = 0.f;
    const int t0 = kh * 200, t1 = t0 + 200;
#pragma unroll 4
    for (int tt = t0; tt < t1; tt++)
        acc += a[tt] * val[((size_t)b * T_ + tt) * KV + k];
    if (kh == 1) cred[k] = acc;
    __syncthreads();
    if (kh == 0) g_ctx[b * KV + k] = acc + cred[k];

    // attn plot (row 0 of batch)
    if (b == 0) {
        const size_t AOFF = (size_t)B * L_ * V_;
        for (int tt = tid; tt < T_; tt += 256)
            out[AOFF + (size_t)t * T_ + tt] = a[tt];
    }
}

// ---------------- final logits for step L-1 ----------------
__global__ __launch_bounds__(256) void k_logits_fin(
    const float* __restrict__ w_out, const float* __restrict__ b_out,
    float* __restrict__ out)
{
    logits_block(blockIdx.x, w_out, b_out, out, L_ - 1);
}

// ---------------- launch ----------------
extern "C" void kernel_launch(void* const* d_in, const int* in_sizes, int n_in,
                              void* d_out, int out_size)
{
    const float* enc_key  = (const float*)d_in[0];
    const float* enc_val  = (const float*)d_in[1];
    const int*   elen     = (const int*)  d_in[2];
    const int*   y        = (const int*)  d_in[3];
    const float* emb      = (const float*)d_in[4];
    const float* w_ih1    = (const float*)d_in[5];
    const float* w_hh1    = (const float*)d_in[6];
    const float* b_ih1    = (const float*)d_in[7];
    const float* b_hh1    = (const float*)d_in[8];
    const float* w_ih2    = (const float*)d_in[9];
    const float* w_hh2    = (const float*)d_in[10];
    const float* b_ih2    = (const float*)d_in[11];
    const float* b_hh2    = (const float*)d_in[12];
    const float* w_out    = (const float*)d_in[13];
    const float* b_out    = (const float*)d_in[14];
    float* out = (float*)d_out;

    k_init<<<256, 256>>>();
    for (int t = 0; t < L_; t++) {
        k_step1<<<192, 256>>>(emb, y, w_ih1, w_hh1, b_ih1, b_hh1, w_out, b_out, out, t);
        k_lstm2<<<B, 256>>>(w_ih2, w_hh2, b_ih2, b_hh2, t);
        k_attn <<<B, 256>>>(enc_key, enc_val, elen, out, t);
    }
    k_logits_fin<<<64, 256>>>(w_out, b_out, out);
}

// round 3
// speedup vs baseline: 3.7078x; 3.7078x over previous
#include <cuda_runtime.h>
#include <math.h>

#define B   128
#define T_  400
#define KV  128
#define V_  1024
#define E_  256
#define H_  512
#define L_  300
#define NEG (-1e9f)

// ---------------- persistent device state ----------------
__device__ float g_h1a[B * H_];
__device__ float g_h1b[B * H_];
__device__ float g_c1 [B * H_];
__device__ float g_h2x[2][B * KV];   // ping-pong: written at step t into g_h2x[t&1]
__device__ float g_c2 [B * KV];
__device__ float g_ctx[B * KV];

__device__ __forceinline__ float sigm(float x) { return 1.0f / (1.0f + expf(-x)); }

// ---------------- init ----------------
__global__ __launch_bounds__(256) void k_init() {
    int stride = gridDim.x * blockDim.x;
    int i0 = blockIdx.x * blockDim.x + threadIdx.x;
    for (int i = i0; i < B * H_; i += stride) { g_h1a[i] = 0.f; g_h1b[i] = 0.f; g_c1[i] = 0.f; }
    for (int i = i0; i < B * KV; i += stride) {
        g_h2x[0][i] = 0.f; g_h2x[1][i] = 0.f; g_c2[i] = 0.f; g_ctx[i] = 0.f;
    }
}

// ---------------- logits block: v-tile(128) x b-tile(16), K=256, smem-staged, double-buffered ----
__device__ void logits_block(int c2, const float* __restrict__ w_out,
                             const float* __restrict__ b_out,
                             const float* __restrict__ h2r,
                             float* __restrict__ out, int tout,
                             float (*xs)[528], float (*ws)[4224])
{
    const int tid = threadIdx.x;
    const int vt = c2 & 7, bt = c2 >> 3;
    const int v0 = vt * 128, b0 = bt * 16;
    const int kk = tid & 31, rb = tid >> 5;
    float ww[16], xw[2];

    auto LD = [&](int it) {
        int k = it * 32 + kk;
#pragma unroll
        for (int j = 0; j < 2; j++) {
            int bb = rb + 8 * j;
            xw[j] = (k < 128) ? h2r[(b0 + bb) * KV + k]
                              : g_ctx[(b0 + bb) * KV + (k - 128)];
        }
#pragma unroll
        for (int j = 0; j < 16; j++) {
            int row = rb + 8 * j;
            ww[j] = w_out[(size_t)(v0 + row) * 256 + k];
        }
    };
    auto ST = [&](int buf) {
#pragma unroll
        for (int j = 0; j < 2; j++)  xs[buf][(rb + 8 * j) * 33 + kk] = xw[j];
#pragma unroll
        for (int j = 0; j < 16; j++) ws[buf][(rb + 8 * j) * 33 + kk] = ww[j];
    };

    float acc[8];
#pragma unroll
    for (int r = 0; r < 8; r++) acc[r] = 0.f;
    const int vl = tid & 127, bg = tid >> 7;

    LD(0); ST(0); __syncthreads();
    for (int it = 0; it < 8; it++) {
        if (it < 7) LD(it + 1);
        const float* wsb = ws[it & 1];
        const float* xsb = xs[it & 1];
#pragma unroll
        for (int k2 = 0; k2 < 32; k2++) {
            float w = wsb[vl * 33 + k2];
#pragma unroll
            for (int r = 0; r < 8; r++) acc[r] += w * xsb[(bg * 8 + r) * 33 + k2];
        }
        if (it < 7) ST((it + 1) & 1);
        __syncthreads();
    }
    const float bo = b_out[v0 + vl];
#pragma unroll
    for (int r = 0; r < 8; r++) {
        int b = b0 + bg * 8 + r;
        out[((size_t)b * L_ + tout) * V_ + (v0 + vl)] = acc[r] + bo;
    }
}

// ---------------- kernel 1: LSTM1(t) on CTAs [0,128) + logits(t-1) on CTAs [128,192) ----
__global__ __launch_bounds__(256) void k_step1(
    const float* __restrict__ emb, const int* __restrict__ y,
    const float* __restrict__ w_ih1, const float* __restrict__ w_hh1,
    const float* __restrict__ b_ih1, const float* __restrict__ b_hh1,
    const float* __restrict__ w_out, const float* __restrict__ b_out,
    float* __restrict__ out, int t)
{
    __shared__ float s_xs[2][528];
    __shared__ float s_ws[2][4224];
    __shared__ int   toks[16];

    const int c = blockIdx.x, tid = threadIdx.x;
    if (c >= 128) {
        if (t > 0)
            logits_block(c - 128, w_out, b_out, g_h2x[(t + 1) & 1], out, t - 1, s_xs, s_ws);
        return;
    }

    const int b0 = (c & 7) * 16, h0 = (c >> 3) * 32;
    const float* __restrict__ h1r = (t & 1) ? g_h1b : g_h1a;
    float* __restrict__       h1w = (t & 1) ? g_h1a : g_h1b;

    if (tid < 16) toks[tid] = (t == 0) ? 1 : y[(b0 + tid) * L_ + (t - 1)];
    __syncthreads();

    const int kk = tid & 31, rb = tid >> 5;
    float ww[16], xw[2];

    auto LD = [&](int it) {
        int k = it * 32 + kk;
#pragma unroll
        for (int j = 0; j < 2; j++) {
            int bb = rb + 8 * j;
            float v;
            if (k < 256)      v = emb[(size_t)toks[bb] * E_ + k];
            else if (k < 384) v = g_ctx[(b0 + bb) * KV + (k - 256)];
            else              v = h1r[(size_t)(b0 + bb) * H_ + (k - 384)];
            xw[j] = v;
        }
#pragma unroll
        for (int j = 0; j < 16; j++) {
            int row = rb + 8 * j;
            int g = row >> 5, hh = row & 31;
            int grow = g * H_ + h0 + hh;
            ww[j] = (k < 384) ? w_ih1[(size_t)grow * 384 + k]
                              : w_hh1[(size_t)grow * H_ + (k - 384)];
        }
    };
    auto ST = [&](int buf) {
#pragma unroll
        for (int j = 0; j < 2; j++)  s_xs[buf][(rb + 8 * j) * 33 + kk] = xw[j];
#pragma unroll
        for (int j = 0; j < 16; j++) s_ws[buf][(rb + 8 * j) * 33 + kk] = ww[j];
    };

    const int hl = tid & 31, bg = tid >> 5;
    const int bA = bg * 2, bB = bA + 1;
    float acc0[4] = {0.f, 0.f, 0.f, 0.f};
    float acc1[4] = {0.f, 0.f, 0.f, 0.f};

    LD(0); ST(0); __syncthreads();
    for (int it = 0; it < 28; it++) {
        if (it < 27) LD(it + 1);
        const float* wsb = s_ws[it & 1];
        const float* xsb = s_xs[it & 1];
#pragma unroll
        for (int k2 = 0; k2 < 32; k2++) {
            float a0 = xsb[bA * 33 + k2];
            float a1 = xsb[bB * 33 + k2];
#pragma unroll
            for (int g = 0; g < 4; g++) {
                float w = wsb[((g << 5) + hl) * 33 + k2];
                acc0[g] += w * a0;
                acc1[g] += w * a1;
            }
        }
        if (it < 27) ST((it + 1) & 1);
        __syncthreads();
    }

    // epilogue: LSTM pointwise
    const int hidx = h0 + hl;
    float bias[4];
#pragma unroll
    for (int g = 0; g < 4; g++) bias[g] = b_ih1[g * H_ + hidx] + b_hh1[g * H_ + hidx];
    {
        int b = b0 + bA;
        float gi = acc0[0] + bias[0], gf = acc0[1] + bias[1];
        float gg = acc0[2] + bias[2], go = acc0[3] + bias[3];
        float co = g_c1[(size_t)b * H_ + hidx];
        float cn = sigm(gf) * co + sigm(gi) * tanhf(gg);
        g_c1[(size_t)b * H_ + hidx] = cn;
        h1w[(size_t)b * H_ + hidx]  = sigm(go) * tanhf(cn);
    }
    {
        int b = b0 + bB;
        float gi = acc1[0] + bias[0], gf = acc1[1] + bias[1];
        float gg = acc1[2] + bias[2], go = acc1[3] + bias[3];
        float co = g_c1[(size_t)b * H_ + hidx];
        float cn = sigm(gf) * co + sigm(gi) * tanhf(gg);
        g_c1[(size_t)b * H_ + hidx] = cn;
        h1w[(size_t)b * H_ + hidx]  = sigm(go) * tanhf(cn);
    }
}

// ---------------- kernel 2: LSTM2 tiled: 8 btiles(16) x 16 htiles(8 units), K=640 ----
__global__ __launch_bounds__(256) void k_lstm2(
    const float* __restrict__ w_ih2, const float* __restrict__ w_hh2,
    const float* __restrict__ bi2,  const float* __restrict__ bh2, int t)
{
    __shared__ float s_xs[2][528];
    __shared__ float s_ws[2][1056];
    __shared__ float gred[32 * 17];

    const int c = blockIdx.x, tid = threadIdx.x;
    const int b0 = (c & 7) * 16, u0 = (c >> 3) * 8;
    const float* __restrict__ h1n = (t & 1) ? g_h1a : g_h1b;   // new h1
    const float* __restrict__ h2r = g_h2x[(t + 1) & 1];        // old h2
    float* __restrict__       h2w = g_h2x[t & 1];              // new h2

    const int kk = tid & 31, rb = tid >> 5;
    float ww[4], xw[2];

    auto LD = [&](int it) {
        int k = it * 32 + kk;
#pragma unroll
        for (int j = 0; j < 2; j++) {
            int bb = rb + 8 * j;
            xw[j] = (k < 512) ? h1n[(size_t)(b0 + bb) * H_ + k]
                              : h2r[(b0 + bb) * KV + (k - 512)];
        }
#pragma unroll
        for (int j = 0; j < 4; j++) {
            int row = rb + 8 * j;            // 0..31 = g*8+u
            int g = row >> 3, u = row & 7;
            int grow = g * KV + u0 + u;
            ww[j] = (k < 512) ? w_ih2[(size_t)grow * H_ + k]
                              : w_hh2[(size_t)grow * KV + (k - 512)];
        }
    };
    auto ST = [&](int buf) {
#pragma unroll
        for (int j = 0; j < 2; j++) s_xs[buf][(rb + 8 * j) * 33 + kk] = xw[j];
#pragma unroll
        for (int j = 0; j < 4; j++) s_ws[buf][(rb + 8 * j) * 33 + kk] = ww[j];
    };

    const int r = tid & 31, bg = tid >> 5;
    const int bA = bg * 2, bB = bA + 1;
    float acc0 = 0.f, acc1 = 0.f;

    LD(0); ST(0); __syncthreads();
    for (int it = 0; it < 20; it++) {
        if (it < 19) LD(it + 1);
        const float* wsb = s_ws[it & 1];
        const float* xsb = s_xs[it & 1];
#pragma unroll
        for (int k2 = 0; k2 < 32; k2++) {
            float w = wsb[r * 33 + k2];
            acc0 += w * xsb[bA * 33 + k2];
            acc1 += w * xsb[bB * 33 + k2];
        }
        if (it < 19) ST((it + 1) & 1);
        __syncthreads();
    }

    gred[r * 17 + bA] = acc0;
    gred[r * 17 + bB] = acc1;
    __syncthreads();

    if (tid < 128) {
        int b = tid >> 3, u = tid & 7;
        int hu = u0 + u;
        float gt[4];
#pragma unroll
        for (int g = 0; g < 4; g++)
            gt[g] = gred[(g * 8 + u) * 17 + b] + bi2[g * KV + hu] + bh2[g * KV + hu];
        int idx = (b0 + b) * KV + hu;
        float co = g_c2[idx];
        float cn = sigm(gt[1]) * co + sigm(gt[0]) * tanhf(gt[2]);
        g_c2[idx] = cn;
        h2w[idx] = sigm(gt[3]) * tanhf(cn);
    }
}

// ---------------- kernel 3: attention, 512 threads, warp-per-row energies ----------------
__global__ __launch_bounds__(512) void k_attn(
    const float* __restrict__ key, const float* __restrict__ val,
    const int* __restrict__ elen, float* __restrict__ out, int t)
{
    const int b = blockIdx.x, tid = threadIdx.x;
    const int lane = tid & 31, warp = tid >> 5;
    __shared__ __align__(16) float q[128];
    __shared__ float a[T_];
    __shared__ float red[32];
    __shared__ float cred[3 * 128];

    const float* __restrict__ h2n = g_h2x[t & 1];
    if (tid < 128) q[tid] = h2n[b * KV + tid];
    __syncthreads();
    const int len = elen[b];

    // energies: one warp per t-row (coalesced 512B/row)
    const float4 qq = ((const float4*)q)[lane];
#pragma unroll 5
    for (int row = warp; row < T_; row += 16) {
        float s;
        if (row < len) {
            float4 k4 = *(const float4*)(key + ((size_t)b * T_ + row) * KV + lane * 4);
            s = k4.x * qq.x + k4.y * qq.y + k4.z * qq.z + k4.w * qq.w;
#pragma unroll
            for (int o = 16; o; o >>= 1) s += __shfl_xor_sync(0xffffffffu, s, o);
        } else s = NEG;
        if (lane == 0) a[row] = s;
    }
    __syncthreads();

    // max reduce
    float m = (tid < T_) ? a[tid] : -3.4e38f;
#pragma unroll
    for (int o = 16; o; o >>= 1) m = fmaxf(m, __shfl_xor_sync(0xffffffffu, m, o));
    if (lane == 0) red[warp] = m;
    __syncthreads();
    if (warp == 0) {
        float v = (lane < 16) ? red[lane] : -3.4e38f;
#pragma unroll
        for (int o = 16; o; o >>= 1) v = fmaxf(v, __shfl_xor_sync(0xffffffffu, v, o));
        if (lane == 0) red[0] = v;
    }
    __syncthreads();
    m = red[0];
    __syncthreads();

    // exp + sum reduce
    float p = 0.f;
    if (tid < T_) { p = expf(a[tid] - m); a[tid] = p; }
    float s = p;
#pragma unroll
    for (int o = 16; o; o >>= 1) s += __shfl_xor_sync(0xffffffffu, s, o);
    if (lane == 0) red[warp] = s;
    __syncthreads();
    if (warp == 0) {
        float v = (lane < 16) ? red[lane] : 0.f;
#pragma unroll
        for (int o = 16; o; o >>= 1) v += __shfl_xor_sync(0xffffffffu, v, o);
        if (lane == 0) red[0] = v;
    }
    __syncthreads();
    const float inv = 1.0f / red[0];
    if (tid < T_) {
        float pn = a[tid] * inv;
        a[tid] = pn;
        if (b == 0) out[(size_t)B * L_ * V_ + (size_t)t * T_ + tid] = pn;
    }
    __syncthreads();

    // context = attn @ value (skip rows >= len: weights are 0 there)
    const int k = tid & 127, kh = tid >> 7;
    float acc = 0.f;
    const int t0 = kh * 100;
    const int t1 = (t0 + 100 < len) ? t0 + 100 : len;
    for (int tt = t0; tt < t1; tt++)
        acc += a[tt] * val[((size_t)b * T_ + tt) * KV + k];
    if (kh) cred[(kh - 1) * 128 + k] = acc;
    __syncthreads();
    if (kh == 0)
        g_ctx[b * KV + k] = acc + cred[k] + cred[128 + k] + cred[256 + k];
}

// ---------------- final logits for step L-1 ----------------
__global__ __launch_bounds__(256) void k_logits_fin(
    const float* __restrict__ w_out, const float* __restrict__ b_out,
    float* __restrict__ out)
{
    __shared__ float s_xs[2][528];
    __shared__ float s_ws[2][4224];
    logits_block(blockIdx.x, w_out, b_out, g_h2x[(L_ - 1) & 1], out, L_ - 1, s_xs, s_ws);
}

// ---------------- launch ----------------
extern "C" void kernel_launch(void* const* d_in, const int* in_sizes, int n_in,
                              void* d_out, int out_size)
{
    const float* enc_key  = (const float*)d_in[0];
    const float* enc_val  = (const float*)d_in[1];
    const int*   elen     = (const int*)  d_in[2];
    const int*   y        = (const int*)  d_in[3];
    const float* emb      = (const float*)d_in[4];
    const float* w_ih1    = (const float*)d_in[5];
    const float* w_hh1    = (const float*)d_in[6];
    const float* b_ih1    = (const float*)d_in[7];
    const float* b_hh1    = (const float*)d_in[8];
    const float* w_ih2    = (const float*)d_in[9];
    const float* w_hh2    = (const float*)d_in[10];
    const float* b_ih2    = (const float*)d_in[11];
    const float* b_hh2    = (const float*)d_in[12];
    const float* w_out    = (const float*)d_in[13];
    const float* b_out    = (const float*)d_in[14];
    float* out = (float*)d_out;

    k_init<<<256, 256>>>();
    for (int t = 0; t < L_; t++) {
        k_step1<<<192, 256>>>(emb, y, w_ih1, w_hh1, b_ih1, b_hh1, w_out, b_out, out, t);
        k_lstm2<<<B, 256>>>(w_ih2, w_hh2, b_ih2, b_hh2, t);
        k_attn <<<B, 512>>>(enc_key, enc_val, elen, out, t);
    }
    k_logits_fin<<<64, 256>>>(w_out, b_out, out);
}

// round 6
// speedup vs baseline: 4.3691x; 1.1783x over previous
#include <cuda_runtime.h>
#include <math.h>

#define B   128
#define T_  400
#define KV  128
#define V_  1024
#define E_  256
#define H_  512
#define L_  300
#define NEG (-1e9f)

// ---------------- persistent device state ----------------
__device__ float g_h1a[B * H_];
__device__ float g_h1b[B * H_];
__device__ float g_c1 [B * H_];
__device__ float g_h2x[2][B * KV];
__device__ float g_c2 [B * KV];
__device__ float g_ctx[B * KV];

// K-major transposed weights (float4 granularity, rows permuted per-CTA):
// wt1[kc][ri], kc in [0,224): ri = htile*128 + g*32 + hl  <->  src row g*512 + htile*32 + hl
__device__ float4 g_wt1[224 * 2048];
// wt2[kc][ri], kc in [0,160): ri = ut*128 + g*32 + ul     <->  src row g*128 + ut*32 + ul
__device__ float4 g_wt2[160 * 512];
// wto[kc][r],  kc in [0,64):  r in [0,1024) identity
__device__ float4 g_wto[64 * 1024];

__device__ __forceinline__ float sigm(float x) { return 1.0f / (1.0f + expf(-x)); }

// ---------------- init ----------------
__global__ __launch_bounds__(256) void k_init() {
    int stride = gridDim.x * blockDim.x;
    int i0 = blockIdx.x * blockDim.x + threadIdx.x;
    for (int i = i0; i < B * H_; i += stride) { g_h1a[i] = 0.f; g_h1b[i] = 0.f; g_c1[i] = 0.f; }
    for (int i = i0; i < B * KV; i += stride) {
        g_h2x[0][i] = 0.f; g_h2x[1][i] = 0.f; g_c2[i] = 0.f; g_ctx[i] = 0.f;
    }
}

// ---------------- prep: build K-major transposed weights ----------------
#define N_WT1 (224 * 2048)
#define N_WT2 (160 * 512)
#define N_WTO (64 * 1024)
__global__ __launch_bounds__(256) void k_prep(
    const float* __restrict__ w_ih1, const float* __restrict__ w_hh1,
    const float* __restrict__ w_ih2, const float* __restrict__ w_hh2,
    const float* __restrict__ w_out)
{
    int idx = blockIdx.x * blockDim.x + threadIdx.x;
    if (idx < N_WT1) {
        int kc = idx >> 11, ri = idx & 2047;
        int htile = ri >> 7, loc = ri & 127;
        int g = loc >> 5, hl = loc & 31;
        int srow = g * H_ + htile * 32 + hl;
        int k = kc * 4;
        float4 v;
        if (k < 384) v = *(const float4*)(w_ih1 + (size_t)srow * 384 + k);
        else         v = *(const float4*)(w_hh1 + (size_t)srow * H_ + (k - 384));
        g_wt1[kc * 2048 + ri] = v;
    } else if (idx < N_WT1 + N_WT2) {
        int j = idx - N_WT1;
        int kc = j >> 9, ri = j & 511;
        int ut = ri >> 7, loc = ri & 127;
        int g = loc >> 5, ul = loc & 31;
        int srow = g * KV + ut * 32 + ul;
        int k = kc * 4;
        float4 v;
        if (k < 512) v = *(const float4*)(w_ih2 + (size_t)srow * H_ + k);
        else         v = *(const float4*)(w_hh2 + (size_t)srow * KV + (k - 512));
        g_wt2[kc * 512 + ri] = v;
    } else {
        int j = idx - N_WT1 - N_WT2;
        if (j < N_WTO) {
            int kc = j >> 10, r = j & 1023;
            g_wto[kc * 1024 + r] = *(const float4*)(w_out + (size_t)r * 256 + kc * 4);
        }
    }
}

// ---------------- logits: 16 CTAs, 512 v-rows x 16 b each, K=256, streamed weights ----
__device__ __forceinline__ void logits_part(
    int c2, const float* __restrict__ b_out, float* __restrict__ out, int t)
{
    // computes logits for step tout = t-1 (requires t >= 1). h2(t-1) = g_h2x[(t+1)&1].
    __shared__ __align__(16) float xsl[16 * 260];
    const int tid = threadIdx.x;
    const int vt = c2 & 1, bt = c2 >> 1;
    const int v0 = vt * 512, b0 = bt * 16;
    const int tout = t - 1;
    const float* __restrict__ h2r = g_h2x[(t + 1) & 1];

    for (int e = tid; e < 16 * 256; e += 256) {
        int bb = e >> 8, kk = e & 255;
        float v = (kk < 128) ? h2r[(b0 + bb) * KV + kk]
                             : g_ctx[(b0 + bb) * KV + (kk - 128)];
        xsl[bb * 260 + kk] = v;
    }
    __syncthreads();

    const int rt = tid & 127, bh = tid >> 7;
    float acc[4][8];
#pragma unroll
    for (int j = 0; j < 4; j++)
#pragma unroll
        for (int jj = 0; jj < 8; jj++) acc[j][jj] = 0.f;

    float4 wq[4][2];
#pragma unroll
    for (int p = 0; p < 2; p++)
#pragma unroll
        for (int j = 0; j < 4; j++)
            wq[j][p] = g_wto[p * 1024 + v0 + j * 128 + rt];

#pragma unroll 2
    for (int kc = 0; kc < 64; kc++) {
        float4 w[4];
#pragma unroll
        for (int j = 0; j < 4; j++) w[j] = wq[j][kc & 1];
        if (kc < 62) {
#pragma unroll
            for (int j = 0; j < 4; j++)
                wq[j][kc & 1] = g_wto[(kc + 2) * 1024 + v0 + j * 128 + rt];
        }
#pragma unroll
        for (int jj = 0; jj < 8; jj++) {
            float4 xv = *(const float4*)(xsl + (bh * 8 + jj) * 260 + kc * 4);
#pragma unroll
            for (int j = 0; j < 4; j++)
                acc[j][jj] += w[j].x * xv.x + w[j].y * xv.y + w[j].z * xv.z + w[j].w * xv.w;
        }
    }

#pragma unroll
    for (int j = 0; j < 4; j++) {
        int r = v0 + j * 128 + rt;
        float bo = b_out[r];
#pragma unroll
        for (int jj = 0; jj < 8; jj++) {
            int b = b0 + bh * 8 + jj;
            __stcs(out + ((size_t)b * L_ + tout) * V_ + r, acc[j][jj] + bo);
        }
    }
}

// ---------------- kernel 1: LSTM1 on CTAs [0,128), logits(t-1) on CTAs [128,144) ----
__global__ __launch_bounds__(256) void k_step1(
    const float* __restrict__ emb, const int* __restrict__ y,
    const float* __restrict__ b_ih1, const float* __restrict__ b_hh1,
    const float* __restrict__ b_out, float* __restrict__ out, int t)
{
    const int c = blockIdx.x, tid = threadIdx.x;
    if (c >= 128) {
        if (t > 0) logits_part(c - 128, b_out, out, t);
        return;
    }

    __shared__ __align__(16) float xs[16 * 132];
    __shared__ float gsm[128 * 17];
    __shared__ int toks[16];

    const int b0 = (c & 7) * 16, ht = c >> 3;
    const float* __restrict__ h1r = (t & 1) ? g_h1b : g_h1a;
    float* __restrict__       h1w = (t & 1) ? g_h1a : g_h1b;

    if (tid < 16) toks[tid] = (t == 0) ? 1 : y[(b0 + tid) * L_ + (t - 1)];

    const int row_t = tid & 127;      // g*32 + hl
    const int bh = tid >> 7;          // batch half (8 b each)
    const int ri = ht * 128 + row_t;

    float acc[8];
#pragma unroll
    for (int j = 0; j < 8; j++) acc[j] = 0.f;

    for (int ch = 0; ch < 7; ch++) {
        __syncthreads();
        // stage activation chunk: k in [ch*128, ch*128+128)
        for (int e = tid; e < 2048; e += 256) {
            int bb = e >> 7, kk = e & 127;
            int k = ch * 128 + kk;
            float v;
            if (k < 256)      v = emb[(size_t)toks[bb] * E_ + k];
            else if (k < 384) v = g_ctx[(b0 + bb) * KV + (k - 256)];
            else              v = h1r[(size_t)(b0 + bb) * H_ + (k - 384)];
            xs[bb * 132 + kk] = v;
        }
        __syncthreads();

        const float4* __restrict__ wp = g_wt1 + (size_t)(ch * 32) * 2048 + ri;
        float4 wq[8];
#pragma unroll
        for (int p = 0; p < 8; p++) wq[p] = wp[(size_t)p * 2048];
#pragma unroll
        for (int kc = 0; kc < 32; kc++) {
            float4 w = wq[kc & 7];
            if (kc < 24) wq[kc & 7] = wp[(size_t)(kc + 8) * 2048];
#pragma unroll
            for (int j = 0; j < 8; j++) {
                float4 xv = *(const float4*)(xs + (bh * 8 + j) * 132 + kc * 4);
                acc[j] += w.x * xv.x + w.y * xv.y + w.z * xv.z + w.w * xv.w;
            }
        }
    }
    __syncthreads();
#pragma unroll
    for (int j = 0; j < 8; j++) gsm[row_t * 17 + bh * 8 + j] = acc[j];
    __syncthreads();

    // pointwise: 32 h x 16 b = 512 cells, 2 per thread
#pragma unroll
    for (int pp = 0; pp < 2; pp++) {
        int cell = tid + pp * 256;
        int hh = cell & 31, bb = cell >> 5;
        int hidx = ht * 32 + hh;
        float gi = gsm[(0 * 32 + hh) * 17 + bb] + b_ih1[0 * H_ + hidx] + b_hh1[0 * H_ + hidx];
        float gf = gsm[(1 * 32 + hh) * 17 + bb] + b_ih1[1 * H_ + hidx] + b_hh1[1 * H_ + hidx];
        float gg = gsm[(2 * 32 + hh) * 17 + bb] + b_ih1[2 * H_ + hidx] + b_hh1[2 * H_ + hidx];
        float go = gsm[(3 * 32 + hh) * 17 + bb] + b_ih1[3 * H_ + hidx] + b_hh1[3 * H_ + hidx];
        int gidx = (b0 + bb) * H_ + hidx;
        float co = g_c1[gidx];
        float cn = sigm(gf) * co + sigm(gi) * tanhf(gg);
        g_c1[gidx] = cn;
        h1w[gidx]  = sigm(go) * tanhf(cn);
    }
}

// ---------------- kernel 2: LSTM2, 64 CTAs (4 unit-tiles x 16 b-tiles of 8) ----------------
__global__ __launch_bounds__(256) void k_lstm2(
    const float* __restrict__ bi2, const float* __restrict__ bh2, int t)
{
    __shared__ __align__(16) float xs[8 * 644];
    __shared__ float gsm[128 * 9];

    const int c = blockIdx.x, tid = threadIdx.x;
    const int ut = c & 3, bt = c >> 2;
    const int b0 = bt * 8, u0 = ut * 32;

    const float* __restrict__ h1n = (t & 1) ? g_h1a : g_h1b;   // new h1
    const float* __restrict__ h2r = g_h2x[(t + 1) & 1];        // old h2
    float* __restrict__       h2w = g_h2x[t & 1];              // new h2

    for (int e = tid; e < 8 * 640; e += 256) {
        int bb = e / 640, kk = e - bb * 640;
        xs[bb * 644 + kk] = (kk < 512) ? h1n[(size_t)(b0 + bb) * H_ + kk]
                                       : h2r[(b0 + bb) * KV + (kk - 512)];
    }
    __syncthreads();

    const int row_t = tid & 127;    // g*32 + ul
    const int bh = tid >> 7;        // 4 b each
    const int ri = ut * 128 + row_t;

    float acc[4] = {0.f, 0.f, 0.f, 0.f};
    float4 wq[8];
#pragma unroll
    for (int p = 0; p < 8; p++) wq[p] = g_wt2[(size_t)p * 512 + ri];
#pragma unroll 8
    for (int kc = 0; kc < 160; kc++) {
        float4 w = wq[kc & 7];
        if (kc < 152) wq[kc & 7] = g_wt2[(size_t)(kc + 8) * 512 + ri];
#pragma unroll
        for (int j = 0; j < 4; j++) {
            float4 xv = *(const float4*)(xs + (bh * 4 + j) * 644 + kc * 4);
            acc[j] += w.x * xv.x + w.y * xv.y + w.z * xv.z + w.w * xv.w;
        }
    }
#pragma unroll
    for (int j = 0; j < 4; j++) gsm[row_t * 9 + bh * 4 + j] = acc[j];
    __syncthreads();

    // pointwise: 32 units x 8 b = 256 cells, 1 per thread
    {
        int u = tid & 31, bb = tid >> 5;
        int hu = u0 + u;
        float gi = gsm[(0 * 32 + u) * 9 + bb] + bi2[0 * KV + hu] + bh2[0 * KV + hu];
        float gf = gsm[(1 * 32 + u) * 9 + bb] + bi2[1 * KV + hu] + bh2[1 * KV + hu];
        float gg = gsm[(2 * 32 + u) * 9 + bb] + bi2[2 * KV + hu] + bh2[2 * KV + hu];
        float go = gsm[(3 * 32 + u) * 9 + bb] + bi2[3 * KV + hu] + bh2[3 * KV + hu];
        int idx = (b0 + bb) * KV + hu;
        float co = g_c2[idx];
        float cn = sigm(gf) * co + sigm(gi) * tanhf(gg);
        g_c2[idx] = cn;
        h2w[idx]  = sigm(go) * tanhf(cn);
    }
}

// ---------------- kernel 3: attention, 512 threads, 4 threads per t-row ----------------
__global__ __launch_bounds__(512) void k_attn(
    const float* __restrict__ key, const float* __restrict__ val,
    const int* __restrict__ elen, float* __restrict__ out, int t)
{
    const int b = blockIdx.x, tid = threadIdx.x;
    const int lane = tid & 31, warp = tid >> 5;
    __shared__ __align__(16) float q[128];
    __shared__ float a[T_];
    __shared__ float red[32];
    __shared__ float cred[3 * 128];

    const float* __restrict__ h2n = g_h2x[t & 1];
    if (tid < 128) q[tid] = h2n[b * KV + tid];
    __syncthreads();
    const int len = elen[b];

    // energies: 4 threads per row, 8 independent float4 loads each (MLP 8).
    // IMPORTANT: no divergent branches around the shuffles — compute for a
    // clamped (always in-bounds) row on every lane, shuffle uniformly, and
    // apply the length mask only at the smem write.
    const int j4 = tid & 3, rb = tid >> 2;       // 128 row-threads
    float4 qf[8];
#pragma unroll
    for (int i = 0; i < 8; i++) qf[i] = *(const float4*)(q + (j4 + 4 * i) * 4);

#pragma unroll
    for (int rr = 0; rr < 4; rr++) {
        int row = rb + rr * 128;                 // covers 0..511; valid < 400
        int rowc = (row < T_) ? row : (T_ - 1);  // clamped, in-bounds load
        const float4* kr = (const float4*)(key + ((size_t)b * T_ + rowc) * KV);
        float s = 0.f;
#pragma unroll
        for (int i = 0; i < 8; i++) {
            float4 kk = kr[j4 + 4 * i];
            s += kk.x * qf[i].x + kk.y * qf[i].y + kk.z * qf[i].z + kk.w * qf[i].w;
        }
        s += __shfl_xor_sync(0xffffffffu, s, 1);
        s += __shfl_xor_sync(0xffffffffu, s, 2);
        if (j4 == 0 && row < T_) a[row] = (row < len) ? s : NEG;
    }
    __syncthreads();

    // max reduce
    float m = (tid < T_) ? a[tid] : -3.4e38f;
#pragma unroll
    for (int o = 16; o; o >>= 1) m = fmaxf(m, __shfl_xor_sync(0xffffffffu, m, o));
    if (lane == 0) red[warp] = m;
    __syncthreads();
    if (warp == 0) {
        float v = (lane < 16) ? red[lane] : -3.4e38f;
#pragma unroll
        for (int o = 16; o; o >>= 1) v = fmaxf(v, __shfl_xor_sync(0xffffffffu, v, o));
        if (lane == 0) red[0] = v;
    }
    __syncthreads();
    m = red[0];
    __syncthreads();

    // exp + sum reduce
    float p = 0.f;
    if (tid < T_) { p = expf(a[tid] - m); a[tid] = p; }
    float s = p;
#pragma unroll
    for (int o = 16; o; o >>= 1) s += __shfl_xor_sync(0xffffffffu, s, o);
    if (lane == 0) red[warp] = s;
    __syncthreads();
    if (warp == 0) {
        float v = (lane < 16) ? red[lane] : 0.f;
#pragma unroll
        for (int o = 16; o; o >>= 1) v += __shfl_xor_sync(0xffffffffu, v, o);
        if (lane == 0) red[0] = v;
    }
    __syncthreads();
    const float inv = 1.0f / red[0];
    if (tid < T_) {
        float pn = a[tid] * inv;
        a[tid] = pn;
        if (b == 0) __stcs(out + (size_t)B * L_ * V_ + (size_t)t * T_ + tid, pn);
    }
    __syncthreads();

    // context = attn @ value over 4 row-segments of 100
    const int k = tid & 127, seg = tid >> 7;
    float acc = 0.f;
    const int t0 = seg * 100;
    int t1 = t0 + 100; if (t1 > len) t1 = len;
#pragma unroll 4
    for (int tt = t0; tt < t1; tt++)
        acc += a[tt] * val[((size_t)b * T_ + tt) * KV + k];
    if (seg) cred[(seg - 1) * 128 + k] = acc;
    __syncthreads();
    if (seg == 0)
        g_ctx[b * KV + k] = acc + cred[k] + cred[128 + k] + cred[256 + k];
}

// ---------------- final logits for step L-1 ----------------
__global__ __launch_bounds__(256) void k_logits_fin(
    const float* __restrict__ b_out, float* __restrict__ out)
{
    logits_part(blockIdx.x, b_out, out, L_);   // tout = L_-1, h2 = g_h2x[(L_+1)&1]
}

// ---------------- launch ----------------
extern "C" void kernel_launch(void* const* d_in, const int* in_sizes, int n_in,
                              void* d_out, int out_size)
{
    const float* enc_key  = (const float*)d_in[0];
    const float* enc_val  = (const float*)d_in[1];
    const int*   elen     = (const int*)  d_in[2];
    const int*   y        = (const int*)  d_in[3];
    const float* emb      = (const float*)d_in[4];
    const float* w_ih1    = (const float*)d_in[5];
    const float* w_hh1    = (const float*)d_in[6];
    const float* b_ih1    = (const float*)d_in[7];
    const float* b_hh1    = (const float*)d_in[8];
    const float* w_ih2    = (const float*)d_in[9];
    const float* w_hh2    = (const float*)d_in[10];
    const float* b_ih2    = (const float*)d_in[11];
    const float* b_hh2    = (const float*)d_in[12];
    const float* w_out    = (const float*)d_in[13];
    const float* b_out    = (const float*)d_in[14];
    float* out = (float*)d_out;

    k_init<<<256, 256>>>();
    k_prep<<<(N_WT1 + N_WT2 + N_WTO + 255) / 256, 256>>>(w_ih1, w_hh1, w_ih2, w_hh2, w_out);
    for (int t = 0; t < L_; t++) {
        k_step1<<<144, 256>>>(emb, y, b_ih1, b_hh1, b_out, out, t);
        k_lstm2<<<64, 256>>>(b_ih2, b_hh2, t);
        k_attn <<<B, 512>>>(enc_key, enc_val, elen, out, t);
    }
    k_logits_fin<<<16, 256>>>(b_out, out);
}

// round 7
// speedup vs baseline: 5.0745x; 1.1615x over previous
#include <cuda_runtime.h>
#include <math.h>

#define B   128
#define T_  400
#define KV  128
#define V_  1024
#define E_  256
#define H_  512
#define L_  300
#define NEG (-1e9f)

typedef unsigned long long u64;

// packed fp32x2 FMA: d.lo += a.lo*b.lo; d.hi += a.hi*b.hi  (exact fp32)
__device__ __forceinline__ void ffma2(u64 &d, u64 a, u64 b) {
    asm("fma.rn.f32x2 %0, %1, %2, %0;" : "+l"(d) : "l"(a), "l"(b));
}
__device__ __forceinline__ float lohi(u64 v) {
    float x, y;
    asm("mov.b64 {%0,%1}, %2;" : "=f"(x), "=f"(y) : "l"(v));
    return x + y;
}

// ---------------- persistent device state ----------------
__device__ float g_h1a[B * H_];
__device__ float g_h1b[B * H_];
__device__ float g_c1 [B * H_];
__device__ float g_h2x[2][B * KV];
__device__ float g_c2 [B * KV];
__device__ float g_ctx[B * KV];
__device__ float g_g2p[4 * B * 512];   // lstm2 partial gate sums [ks][b][g*128+u]

// K-major transposed weights (float4 granularity, rows permuted per-CTA):
__device__ float4 g_wt1[224 * 2048];
__device__ float4 g_wt2[160 * 512];
__device__ float4 g_wto[64 * 1024];

__device__ __forceinline__ float sigm(float x) { return 1.0f / (1.0f + expf(-x)); }

// ---------------- init ----------------
__global__ __launch_bounds__(256) void k_init() {
    int stride = gridDim.x * blockDim.x;
    int i0 = blockIdx.x * blockDim.x + threadIdx.x;
    for (int i = i0; i < B * H_; i += stride) { g_h1a[i] = 0.f; g_h1b[i] = 0.f; g_c1[i] = 0.f; }
    for (int i = i0; i < B * KV; i += stride) {
        g_h2x[0][i] = 0.f; g_h2x[1][i] = 0.f; g_c2[i] = 0.f; g_ctx[i] = 0.f;
    }
}

// ---------------- prep: build K-major transposed weights ----------------
#define N_WT1 (224 * 2048)
#define N_WT2 (160 * 512)
#define N_WTO (64 * 1024)
__global__ __launch_bounds__(256) void k_prep(
    const float* __restrict__ w_ih1, const float* __restrict__ w_hh1,
    const float* __restrict__ w_ih2, const float* __restrict__ w_hh2,
    const float* __restrict__ w_out)
{
    int idx = blockIdx.x * blockDim.x + threadIdx.x;
    if (idx < N_WT1) {
        int kc = idx >> 11, ri = idx & 2047;
        int htile = ri >> 7, loc = ri & 127;
        int g = loc >> 5, hl = loc & 31;
        int srow = g * H_ + htile * 32 + hl;
        int k = kc * 4;
        float4 v;
        if (k < 384) v = *(const float4*)(w_ih1 + (size_t)srow * 384 + k);
        else         v = *(const float4*)(w_hh1 + (size_t)srow * H_ + (k - 384));
        g_wt1[kc * 2048 + ri] = v;
    } else if (idx < N_WT1 + N_WT2) {
        int j = idx - N_WT1;
        int kc = j >> 9, ri = j & 511;
        int ut = ri >> 7, loc = ri & 127;
        int g = loc >> 5, ul = loc & 31;
        int srow = g * KV + ut * 32 + ul;
        int k = kc * 4;
        float4 v;
        if (k < 512) v = *(const float4*)(w_ih2 + (size_t)srow * H_ + k);
        else         v = *(const float4*)(w_hh2 + (size_t)srow * KV + (k - 512));
        g_wt2[kc * 512 + ri] = v;
    } else {
        int j = idx - N_WT1 - N_WT2;
        if (j < N_WTO) {
            int kc = j >> 10, r = j & 1023;
            g_wto[kc * 1024 + r] = *(const float4*)(w_out + (size_t)r * 256 + kc * 4);
        }
    }
}

// ---------------- logits: 16 CTAs, 512 v-rows x 16 b each, K=256, FFMA2 ----
__device__ __forceinline__ void logits_part(
    int c2, const float* __restrict__ b_out, float* __restrict__ out, int t)
{
    // logits for step tout = t-1 (t >= 1). h2(t-1) = g_h2x[(t+1)&1].
    __shared__ __align__(16) float xsl[16 * 260];
    const int tid = threadIdx.x;
    const int vt = c2 & 1, bt = c2 >> 1;
    const int v0 = vt * 512, b0 = bt * 16;
    const int tout = t - 1;
    const float* __restrict__ h2r = g_h2x[(t + 1) & 1];

    for (int e = tid; e < 16 * 256; e += 256) {
        int bb = e >> 8, kk = e & 255;
        float v = (kk < 128) ? h2r[(b0 + bb) * KV + kk]
                             : g_ctx[(b0 + bb) * KV + (kk - 128)];
        xsl[bb * 260 + kk] = v;
    }
    __syncthreads();

    const int rt = tid & 127, bh = tid >> 7;
    u64 acc2[4][8];
#pragma unroll
    for (int j = 0; j < 4; j++)
#pragma unroll
        for (int jj = 0; jj < 8; jj++) acc2[j][jj] = 0ull;

    const ulonglong2* __restrict__ wb = (const ulonglong2*)g_wto;
    ulonglong2 wq[4][2];
#pragma unroll
    for (int p = 0; p < 2; p++)
#pragma unroll
        for (int j = 0; j < 4; j++)
            wq[j][p] = wb[p * 1024 + v0 + j * 128 + rt];

#pragma unroll 2
    for (int kc = 0; kc < 64; kc++) {
        ulonglong2 w[4];
#pragma unroll
        for (int j = 0; j < 4; j++) w[j] = wq[j][kc & 1];
        if (kc < 62) {
#pragma unroll
            for (int j = 0; j < 4; j++)
                wq[j][kc & 1] = wb[(kc + 2) * 1024 + v0 + j * 128 + rt];
        }
#pragma unroll
        for (int jj = 0; jj < 8; jj++) {
            ulonglong2 xv = *(const ulonglong2*)(xsl + (bh * 8 + jj) * 260 + kc * 4);
#pragma unroll
            for (int j = 0; j < 4; j++) {
                ffma2(acc2[j][jj], w[j].x, xv.x);
                ffma2(acc2[j][jj], w[j].y, xv.y);
            }
        }
    }

#pragma unroll
    for (int j = 0; j < 4; j++) {
        int r = v0 + j * 128 + rt;
        float bo = b_out[r];
#pragma unroll
        for (int jj = 0; jj < 8; jj++) {
            int b = b0 + bh * 8 + jj;
            __stcs(out + ((size_t)b * L_ + tout) * V_ + r, lohi(acc2[j][jj]) + bo);
        }
    }
}

// ---------------- kernel 1: LSTM1 on CTAs [0,128), logits(t-1) on CTAs [128,144) ----
__global__ __launch_bounds__(256) void k_step1(
    const float* __restrict__ emb, const int* __restrict__ y,
    const float* __restrict__ b_ih1, const float* __restrict__ b_hh1,
    const float* __restrict__ b_out, float* __restrict__ out, int t)
{
    const int c = blockIdx.x, tid = threadIdx.x;
    if (c >= 128) {
        if (t > 0) logits_part(c - 128, b_out, out, t);
        return;
    }

    __shared__ __align__(16) float xs[16 * 132];
    __shared__ float gsm[128 * 17];
    __shared__ int toks[16];

    const int b0 = (c & 7) * 16, ht = c >> 3;
    const float* __restrict__ h1r = (t & 1) ? g_h1b : g_h1a;
    float* __restrict__       h1w = (t & 1) ? g_h1a : g_h1b;

    if (tid < 16) toks[tid] = (t == 0) ? 1 : y[(b0 + tid) * L_ + (t - 1)];

    const int row_t = tid & 127;      // g*32 + hl
    const int bh = tid >> 7;          // batch half (8 b each)
    const int ri = ht * 128 + row_t;

    u64 acc2[8];
#pragma unroll
    for (int j = 0; j < 8; j++) acc2[j] = 0ull;

    for (int ch = 0; ch < 7; ch++) {
        __syncthreads();
        for (int e = tid; e < 2048; e += 256) {
            int bb = e >> 7, kk = e & 127;
            int k = ch * 128 + kk;
            float v;
            if (k < 256)      v = emb[(size_t)toks[bb] * E_ + k];
            else if (k < 384) v = g_ctx[(b0 + bb) * KV + (k - 256)];
            else              v = h1r[(size_t)(b0 + bb) * H_ + (k - 384)];
            xs[bb * 132 + kk] = v;
        }
        __syncthreads();

        const ulonglong2* __restrict__ wp =
            (const ulonglong2*)(g_wt1 + (size_t)(ch * 32) * 2048 + ri);
        ulonglong2 wq[8];
#pragma unroll
        for (int p = 0; p < 8; p++) wq[p] = wp[(size_t)p * 2048];
#pragma unroll
        for (int kc = 0; kc < 32; kc++) {
            ulonglong2 w = wq[kc & 7];
            if (kc < 24) wq[kc & 7] = wp[(size_t)(kc + 8) * 2048];
#pragma unroll
            for (int j = 0; j < 8; j++) {
                ulonglong2 xv = *(const ulonglong2*)(xs + (bh * 8 + j) * 132 + kc * 4);
                ffma2(acc2[j], w.x, xv.x);
                ffma2(acc2[j], w.y, xv.y);
            }
        }
    }
    __syncthreads();
#pragma unroll
    for (int j = 0; j < 8; j++) gsm[row_t * 17 + bh * 8 + j] = lohi(acc2[j]);
    __syncthreads();

    // pointwise: 32 h x 16 b = 512 cells, 2 per thread
#pragma unroll
    for (int pp = 0; pp < 2; pp++) {
        int cell = tid + pp * 256;
        int hh = cell & 31, bb = cell >> 5;
        int hidx = ht * 32 + hh;
        float gi = gsm[(0 * 32 + hh) * 17 + bb] + b_ih1[0 * H_ + hidx] + b_hh1[0 * H_ + hidx];
        float gf = gsm[(1 * 32 + hh) * 17 + bb] + b_ih1[1 * H_ + hidx] + b_hh1[1 * H_ + hidx];
        float gg = gsm[(2 * 32 + hh) * 17 + bb] + b_ih1[2 * H_ + hidx] + b_hh1[2 * H_ + hidx];
        float go = gsm[(3 * 32 + hh) * 17 + bb] + b_ih1[3 * H_ + hidx] + b_hh1[3 * H_ + hidx];
        int gidx = (b0 + bb) * H_ + hidx;
        float co = g_c1[gidx];
        float cn = sigm(gf) * co + sigm(gi) * tanhf(gg);
        g_c1[gidx] = cn;
        h1w[gidx]  = sigm(go) * tanhf(cn);
    }
}

// ---------------- kernel 2: LSTM2 partial gates, 128 CTAs (4 ks x 4 ut x 8 bt of 16) ----
__global__ __launch_bounds__(256) void k_lstm2p(int t)
{
    __shared__ __align__(16) float xs[16 * 164];

    const int c = blockIdx.x, tid = threadIdx.x;
    const int ks = c >> 5, ut = (c >> 3) & 3, bt = c & 7;
    const int b0 = bt * 16, k0 = ks * 160;

    const float* __restrict__ h1n = (t & 1) ? g_h1a : g_h1b;   // new h1
    const float* __restrict__ h2r = g_h2x[(t + 1) & 1];        // old h2

    for (int e = tid; e < 16 * 160; e += 256) {
        int bb = e / 160, kk = e - bb * 160;
        int k = k0 + kk;
        xs[bb * 164 + kk] = (k < 512) ? h1n[(size_t)(b0 + bb) * H_ + k]
                                      : h2r[(b0 + bb) * KV + (k - 512)];
    }
    __syncthreads();

    const int row_t = tid & 127;     // g*32 + ul within ut
    const int bh = tid >> 7;         // 8 b each
    const int ri = ut * 128 + row_t;

    u64 acc2[8];
#pragma unroll
    for (int j = 0; j < 8; j++) acc2[j] = 0ull;

    const ulonglong2* __restrict__ wp =
        (const ulonglong2*)(g_wt2 + (size_t)(ks * 40) * 512 + ri);
    ulonglong2 wq[8];
#pragma unroll
    for (int p = 0; p < 8; p++) wq[p] = wp[(size_t)p * 512];
#pragma unroll 4
    for (int kc = 0; kc < 40; kc++) {
        ulonglong2 w = wq[kc & 7];
        if (kc < 32) wq[kc & 7] = wp[(size_t)(kc + 8) * 512];
#pragma unroll
        for (int j = 0; j < 8; j++) {
            ulonglong2 xv = *(const ulonglong2*)(xs + (bh * 8 + j) * 164 + kc * 4);
            ffma2(acc2[j], w.x, xv.x);
            ffma2(acc2[j], w.y, xv.y);
        }
    }

    const int gidx = (row_t >> 5) * 128 + ut * 32 + (row_t & 31);
#pragma unroll
    for (int j = 0; j < 8; j++)
        g_g2p[ks * (B * 512) + (b0 + bh * 8 + j) * 512 + gidx] = lohi(acc2[j]);
}

// ---------------- kernel 3: lstm2 finish + attention (1 CTA per b, 512 thr) ----------------
__global__ __launch_bounds__(512) void k_attn(
    const float* __restrict__ key, const float* __restrict__ val,
    const int* __restrict__ elen,
    const float* __restrict__ bi2, const float* __restrict__ bh2,
    float* __restrict__ out, int t)
{
    const int b = blockIdx.x, tid = threadIdx.x;
    const int lane = tid & 31, warp = tid >> 5;
    __shared__ __align__(16) float q[128];
    __shared__ float gates[512];
    __shared__ float a[T_];
    __shared__ float red[32];
    __shared__ float cred[3 * 128];

    // ---- lstm2 finish: reduce 4 partials + biases, pointwise ----
    {
        float gsum = g_g2p[0 * (B * 512) + b * 512 + tid]
                   + g_g2p[1 * (B * 512) + b * 512 + tid]
                   + g_g2p[2 * (B * 512) + b * 512 + tid]
                   + g_g2p[3 * (B * 512) + b * 512 + tid];
        gates[tid] = gsum + bi2[tid] + bh2[tid];
    }
    __syncthreads();
    if (tid < 128) {
        float gi = gates[tid], gf = gates[128 + tid];
        float gg = gates[256 + tid], go = gates[384 + tid];
        int idx = b * KV + tid;
        float co = g_c2[idx];
        float cn = sigm(gf) * co + sigm(gi) * tanhf(gg);
        g_c2[idx] = cn;
        float h = sigm(go) * tanhf(cn);
        g_h2x[t & 1][idx] = h;
        q[tid] = h;
    }
    __syncthreads();

    const int len = elen[b];

    // ---- energies: 4 threads per row, FFMA2, uniform shuffles ----
    const int j4 = tid & 3, rb = tid >> 2;
    ulonglong2 qf[4];
#pragma unroll
    for (int i = 0; i < 4; i++) qf[i] = *(const ulonglong2*)(q + (j4 + 4 * i) * 8);

#pragma unroll
    for (int rr = 0; rr < 4; rr++) {
        int row = rb + rr * 128;
        int rowc = (row < T_) ? row : (T_ - 1);
        const ulonglong2* kr = (const ulonglong2*)(key + ((size_t)b * T_ + rowc) * KV);
        u64 s2 = 0ull;
#pragma unroll
        for (int i = 0; i < 4; i++) {
            ulonglong2 kk = kr[j4 * 2 + 8 * i];
            ulonglong2 k2 = kr[j4 * 2 + 8 * i + 1];
            ffma2(s2, kk.x, qf[i].x);
            ffma2(s2, kk.y, qf[i].y);
            // note: qf[i] covers floats (j4+4i)*8 .. +7 = two ulonglong2? no:
            // ulonglong2 = 4 floats; we need 8 floats per i -> second pair below
            (void)k2;
        }
        // redo cleanly below
        float s;
        {
            u64 t2 = 0ull;
            const ulonglong2* qv = (const ulonglong2*)q;
#pragma unroll
            for (int i = 0; i < 8; i++) {
                ulonglong2 kk = kr[j4 + 4 * i];
                ulonglong2 qq = qv[j4 + 4 * i];
                ffma2(t2, kk.x, qq.x);
                ffma2(t2, kk.y, qq.y);
            }
            s = lohi(t2);
        }
        s += __shfl_xor_sync(0xffffffffu, s, 1);
        s += __shfl_xor_sync(0xffffffffu, s, 2);
        if (j4 == 0 && row < T_) a[row] = (row < len) ? s : NEG;
    }
    __syncthreads();

    // ---- max reduce ----
    float m = (tid < T_) ? a[tid] : -3.4e38f;
#pragma unroll
    for (int o = 16; o; o >>= 1) m = fmaxf(m, __shfl_xor_sync(0xffffffffu, m, o));
    if (lane == 0) red[warp] = m;
    __syncthreads();
    if (warp == 0) {
        float v = (lane < 16) ? red[lane] : -3.4e38f;
#pragma unroll
        for (int o = 16; o; o >>= 1) v = fmaxf(v, __shfl_xor_sync(0xffffffffu, v, o));
        if (lane == 0) red[0] = v;
    }
    __syncthreads();
    m = red[0];
    __syncthreads();

    // ---- exp + sum reduce ----
    float p = 0.f;
    if (tid < T_) { p = expf(a[tid] - m); a[tid] = p; }
    float s = p;
#pragma unroll
    for (int o = 16; o; o >>= 1) s += __shfl_xor_sync(0xffffffffu, s, o);
    if (lane == 0) red[warp] = s;
    __syncthreads();
    if (warp == 0) {
        float v = (lane < 16) ? red[lane] : 0.f;
#pragma unroll
        for (int o = 16; o; o >>= 1) v += __shfl_xor_sync(0xffffffffu, v, o);
        if (lane == 0) red[0] = v;
    }
    __syncthreads();
    const float inv = 1.0f / red[0];
    if (tid < T_) {
        float pn = a[tid] * inv;
        a[tid] = pn;
        if (b == 0) __stcs(out + (size_t)B * L_ * V_ + (size_t)t * T_ + tid, pn);
    }
    __syncthreads();

    // ---- context = attn @ value over 4 row-segments of 100 ----
    const int k = tid & 127, seg = tid >> 7;
    float acc = 0.f;
    const int t0 = seg * 100;
    int t1 = t0 + 100; if (t1 > len) t1 = len;
#pragma unroll 8
    for (int tt = t0; tt < t1; tt++)
        acc += a[tt] * val[((size_t)b * T_ + tt) * KV + k];
    if (seg) cred[(seg - 1) * 128 + k] = acc;
    __syncthreads();
    if (seg == 0)
        g_ctx[b * KV + k] = acc + cred[k] + cred[128 + k] + cred[256 + k];
}

// ---------------- final logits for step L-1 ----------------
__global__ __launch_bounds__(256) void k_logits_fin(
    const float* __restrict__ b_out, float* __restrict__ out)
{
    logits_part(blockIdx.x, b_out, out, L_);   // tout = L_-1, h2 = g_h2x[(L_+1)&1]
}

// ---------------- launch ----------------
extern "C" void kernel_launch(void* const* d_in, const int* in_sizes, int n_in,
                              void* d_out, int out_size)
{
    const float* enc_key  = (const float*)d_in[0];
    const float* enc_val  = (const float*)d_in[1];
    const int*   elen     = (const int*)  d_in[2];
    const int*   y        = (const int*)  d_in[3];
    const float* emb      = (const float*)d_in[4];
    const float* w_ih1    = (const float*)d_in[5];
    const float* w_hh1    = (const float*)d_in[6];
    const float* b_ih1    = (const float*)d_in[7];
    const float* b_hh1    = (const float*)d_in[8];
    const float* w_ih2    = (const float*)d_in[9];
    const float* w_hh2    = (const float*)d_in[10];
    const float* b_ih2    = (const float*)d_in[11];
    const float* b_hh2    = (const float*)d_in[12];
    const float* w_out    = (const float*)d_in[13];
    const float* b_out    = (const float*)d_in[14];
    float* out = (float*)d_out;

    k_init<<<256, 256>>>();
    k_prep<<<(N_WT1 + N_WT2 + N_WTO + 255) / 256, 256>>>(w_ih1, w_hh1, w_ih2, w_hh2, w_out);
    for (int t = 0; t < L_; t++) {
        k_step1<<<144, 256>>>(emb, y, b_ih1, b_hh1, b_out, out, t);
        k_lstm2p<<<128, 256>>>(t);
        k_attn <<<B, 512>>>(enc_key, enc_val, elen, b_ih2, b_hh2, out, t);
    }
    k_logits_fin<<<16, 256>>>(b_out, out);
}

// round 8
// speedup vs baseline: 5.3434x; 1.0530x over previous
#include <cuda_runtime.h>
#include <math.h>

#define B   128
#define T_  400
#define KV  128
#define V_  1024
#define E_  256
#define H_  512
#define L_  300
#define NEG (-1e9f)

typedef unsigned long long u64;

// packed fp32x2 FMA: d.lo += a.lo*b.lo; d.hi += a.hi*b.hi  (exact fp32)
__device__ __forceinline__ void ffma2(u64 &d, u64 a, u64 b) {
    asm("fma.rn.f32x2 %0, %1, %2, %0;" : "+l"(d) : "l"(a), "l"(b));
}
__device__ __forceinline__ float lohi(u64 v) {
    float x, y;
    asm("mov.b64 {%0,%1}, %2;" : "=f"(x), "=f"(y) : "l"(v));
    return x + y;
}

// ---------------- persistent device state ----------------
__device__ float g_h1a[B * H_];
__device__ float g_h1b[B * H_];
__device__ float g_c1 [B * H_];
__device__ float g_h2x[2][B * KV];
__device__ float g_c2 [B * KV];
__device__ float g_ctx[B * KV];
__device__ float g_g2p[4 * B * 512];   // lstm2 partial gate sums [ks][b][g*128+u]

// K-major transposed weights (float4 granularity, rows permuted per-CTA):
__device__ float4 g_wt1[224 * 2048];
__device__ float4 g_wt2[160 * 512];
__device__ float4 g_wto[64 * 1024];

__device__ __forceinline__ float sigm(float x) { return 1.0f / (1.0f + expf(-x)); }

// ---------------- init ----------------
__global__ __launch_bounds__(256) void k_init() {
    int stride = gridDim.x * blockDim.x;
    int i0 = blockIdx.x * blockDim.x + threadIdx.x;
    for (int i = i0; i < B * H_; i += stride) { g_h1a[i] = 0.f; g_h1b[i] = 0.f; g_c1[i] = 0.f; }
    for (int i = i0; i < B * KV; i += stride) {
        g_h2x[0][i] = 0.f; g_h2x[1][i] = 0.f; g_c2[i] = 0.f; g_ctx[i] = 0.f;
    }
}

// ---------------- prep: build K-major transposed weights ----------------
#define N_WT1 (224 * 2048)
#define N_WT2 (160 * 512)
#define N_WTO (64 * 1024)
__global__ __launch_bounds__(256) void k_prep(
    const float* __restrict__ w_ih1, const float* __restrict__ w_hh1,
    const float* __restrict__ w_ih2, const float* __restrict__ w_hh2,
    const float* __restrict__ w_out)
{
    int idx = blockIdx.x * blockDim.x + threadIdx.x;
    if (idx < N_WT1) {
        int kc = idx >> 11, ri = idx & 2047;
        int htile = ri >> 7, loc = ri & 127;
        int g = loc >> 5, hl = loc & 31;
        int srow = g * H_ + htile * 32 + hl;
        int k = kc * 4;
        float4 v;
        if (k < 384) v = *(const float4*)(w_ih1 + (size_t)srow * 384 + k);
        else         v = *(const float4*)(w_hh1 + (size_t)srow * H_ + (k - 384));
        g_wt1[kc * 2048 + ri] = v;
    } else if (idx < N_WT1 + N_WT2) {
        int j = idx - N_WT1;
        int kc = j >> 9, ri = j & 511;
        int ut = ri >> 7, loc = ri & 127;
        int g = loc >> 5, ul = loc & 31;
        int srow = g * KV + ut * 32 + ul;
        int k = kc * 4;
        float4 v;
        if (k < 512) v = *(const float4*)(w_ih2 + (size_t)srow * H_ + k);
        else         v = *(const float4*)(w_hh2 + (size_t)srow * KV + (k - 512));
        g_wt2[kc * 512 + ri] = v;
    } else {
        int j = idx - N_WT1 - N_WT2;
        if (j < N_WTO) {
            int kc = j >> 10, r = j & 1023;
            g_wto[kc * 1024 + r] = *(const float4*)(w_out + (size_t)r * 256 + kc * 4);
        }
    }
}

// ---------------- logits: 16 CTAs, 512 v-rows x 16 b each, K=256, FFMA2 ----
__device__ __forceinline__ void logits_part(
    int c2, const float* __restrict__ b_out, float* __restrict__ out, int t)
{
    // logits for step tout = t-1 (t >= 1). h2(t-1) = g_h2x[(t+1)&1].
    __shared__ __align__(16) float xsl[16 * 260];
    const int tid = threadIdx.x;
    const int vt = c2 & 1, bt = c2 >> 1;
    const int v0 = vt * 512, b0 = bt * 16;
    const int tout = t - 1;
    const float* __restrict__ h2r = g_h2x[(t + 1) & 1];

    for (int e = tid; e < 16 * 256; e += 256) {
        int bb = e >> 8, kk = e & 255;
        float v = (kk < 128) ? h2r[(b0 + bb) * KV + kk]
                             : g_ctx[(b0 + bb) * KV + (kk - 128)];
        xsl[bb * 260 + kk] = v;
    }
    __syncthreads();

    const int rt = tid & 127, bh = tid >> 7;
    u64 acc2[4][8];
#pragma unroll
    for (int j = 0; j < 4; j++)
#pragma unroll
        for (int jj = 0; jj < 8; jj++) acc2[j][jj] = 0ull;

    const ulonglong2* __restrict__ wb = (const ulonglong2*)g_wto;
    ulonglong2 wq[4][2];
#pragma unroll
    for (int p = 0; p < 2; p++)
#pragma unroll
        for (int j = 0; j < 4; j++)
            wq[j][p] = wb[p * 1024 + v0 + j * 128 + rt];

#pragma unroll 2
    for (int kc = 0; kc < 64; kc++) {
        ulonglong2 w[4];
#pragma unroll
        for (int j = 0; j < 4; j++) w[j] = wq[j][kc & 1];
        if (kc < 62) {
#pragma unroll
            for (int j = 0; j < 4; j++)
                wq[j][kc & 1] = wb[(kc + 2) * 1024 + v0 + j * 128 + rt];
        }
#pragma unroll
        for (int jj = 0; jj < 8; jj++) {
            ulonglong2 xv = *(const ulonglong2*)(xsl + (bh * 8 + jj) * 260 + kc * 4);
#pragma unroll
            for (int j = 0; j < 4; j++) {
                ffma2(acc2[j][jj], w[j].x, xv.x);
                ffma2(acc2[j][jj], w[j].y, xv.y);
            }
        }
    }

#pragma unroll
    for (int j = 0; j < 4; j++) {
        int r = v0 + j * 128 + rt;
        float bo = b_out[r];
#pragma unroll
        for (int jj = 0; jj < 8; jj++) {
            int b = b0 + bh * 8 + jj;
            __stcs(out + ((size_t)b * L_ + tout) * V_ + r, lohi(acc2[j][jj]) + bo);
        }
    }
}

// ---------------- kernel 1: LSTM1 on CTAs [0,128), logits(t-1) on CTAs [128,144) ----
__global__ __launch_bounds__(256) void k_step1(
    const float* __restrict__ emb, const int* __restrict__ y,
    const float* __restrict__ b_ih1, const float* __restrict__ b_hh1,
    const float* __restrict__ b_out, float* __restrict__ out, int t)
{
    const int c = blockIdx.x, tid = threadIdx.x;
    if (c >= 128) {
        if (t > 0) logits_part(c - 128, b_out, out, t);
        return;
    }

    __shared__ __align__(16) float xs[16 * 132];
    __shared__ float gsm[128 * 17];
    __shared__ int toks[16];

    const int b0 = (c & 7) * 16, ht = c >> 3;
    const float* __restrict__ h1r = (t & 1) ? g_h1b : g_h1a;
    float* __restrict__       h1w = (t & 1) ? g_h1a : g_h1b;

    if (tid < 16) toks[tid] = (t == 0) ? 1 : y[(b0 + tid) * L_ + (t - 1)];

    const int row_t = tid & 127;      // g*32 + hl
    const int bh = tid >> 7;          // batch half (8 b each)
    const int ri = ht * 128 + row_t;

    u64 acc2[8];
#pragma unroll
    for (int j = 0; j < 8; j++) acc2[j] = 0ull;

    for (int ch = 0; ch < 7; ch++) {
        __syncthreads();
        for (int e = tid; e < 2048; e += 256) {
            int bb = e >> 7, kk = e & 127;
            int k = ch * 128 + kk;
            float v;
            if (k < 256)      v = emb[(size_t)toks[bb] * E_ + k];
            else if (k < 384) v = g_ctx[(b0 + bb) * KV + (k - 256)];
            else              v = h1r[(size_t)(b0 + bb) * H_ + (k - 384)];
            xs[bb * 132 + kk] = v;
        }
        __syncthreads();

        const ulonglong2* __restrict__ wp =
            (const ulonglong2*)(g_wt1 + (size_t)(ch * 32) * 2048 + ri);
        ulonglong2 wq[8];
#pragma unroll
        for (int p = 0; p < 8; p++) wq[p] = wp[(size_t)p * 2048];
#pragma unroll
        for (int kc = 0; kc < 32; kc++) {
            ulonglong2 w = wq[kc & 7];
            if (kc < 24) wq[kc & 7] = wp[(size_t)(kc + 8) * 2048];
#pragma unroll
            for (int j = 0; j < 8; j++) {
                ulonglong2 xv = *(const ulonglong2*)(xs + (bh * 8 + j) * 132 + kc * 4);
                ffma2(acc2[j], w.x, xv.x);
                ffma2(acc2[j], w.y, xv.y);
            }
        }
    }
    __syncthreads();
#pragma unroll
    for (int j = 0; j < 8; j++) gsm[row_t * 17 + bh * 8 + j] = lohi(acc2[j]);
    __syncthreads();

    // pointwise: 32 h x 16 b = 512 cells, 2 per thread
#pragma unroll
    for (int pp = 0; pp < 2; pp++) {
        int cell = tid + pp * 256;
        int hh = cell & 31, bb = cell >> 5;
        int hidx = ht * 32 + hh;
        float gi = gsm[(0 * 32 + hh) * 17 + bb] + b_ih1[0 * H_ + hidx] + b_hh1[0 * H_ + hidx];
        float gf = gsm[(1 * 32 + hh) * 17 + bb] + b_ih1[1 * H_ + hidx] + b_hh1[1 * H_ + hidx];
        float gg = gsm[(2 * 32 + hh) * 17 + bb] + b_ih1[2 * H_ + hidx] + b_hh1[2 * H_ + hidx];
        float go = gsm[(3 * 32 + hh) * 17 + bb] + b_ih1[3 * H_ + hidx] + b_hh1[3 * H_ + hidx];
        int gidx = (b0 + bb) * H_ + hidx;
        float co = g_c1[gidx];
        float cn = sigm(gf) * co + sigm(gi) * tanhf(gg);
        g_c1[gidx] = cn;
        h1w[gidx]  = sigm(go) * tanhf(cn);
    }
}

// ---------------- kernel 2: LSTM2 partial gates, 128 CTAs (4 ks x 4 ut x 8 bt of 16) ----
__global__ __launch_bounds__(256) void k_lstm2p(int t)
{
    __shared__ __align__(16) float xs[16 * 164];

    const int c = blockIdx.x, tid = threadIdx.x;
    const int ks = c >> 5, ut = (c >> 3) & 3, bt = c & 7;
    const int b0 = bt * 16, k0 = ks * 160;

    const float* __restrict__ h1n = (t & 1) ? g_h1a : g_h1b;   // new h1
    const float* __restrict__ h2r = g_h2x[(t + 1) & 1];        // old h2

    for (int e = tid; e < 16 * 160; e += 256) {
        int bb = e / 160, kk = e - bb * 160;
        int k = k0 + kk;
        xs[bb * 164 + kk] = (k < 512) ? h1n[(size_t)(b0 + bb) * H_ + k]
                                      : h2r[(b0 + bb) * KV + (k - 512)];
    }
    __syncthreads();

    const int row_t = tid & 127;     // g*32 + ul within ut
    const int bh = tid >> 7;         // 8 b each
    const int ri = ut * 128 + row_t;

    u64 acc2[8];
#pragma unroll
    for (int j = 0; j < 8; j++) acc2[j] = 0ull;

    const ulonglong2* __restrict__ wp =
        (const ulonglong2*)(g_wt2 + (size_t)(ks * 40) * 512 + ri);
    ulonglong2 wq[8];
#pragma unroll
    for (int p = 0; p < 8; p++) wq[p] = wp[(size_t)p * 512];
    // FULL unroll: ring index kc&7 must be compile-time constant, otherwise
    // wq[] is demoted to local memory (the round-7 24.6us pathology).
#pragma unroll
    for (int kc = 0; kc < 40; kc++) {
        ulonglong2 w = wq[kc & 7];
        if (kc < 32) wq[kc & 7] = wp[(size_t)(kc + 8) * 512];
#pragma unroll
        for (int j = 0; j < 8; j++) {
            ulonglong2 xv = *(const ulonglong2*)(xs + (bh * 8 + j) * 164 + kc * 4);
            ffma2(acc2[j], w.x, xv.x);
            ffma2(acc2[j], w.y, xv.y);
        }
    }

    const int gidx = (row_t >> 5) * 128 + ut * 32 + (row_t & 31);
#pragma unroll
    for (int j = 0; j < 8; j++)
        g_g2p[ks * (B * 512) + (b0 + bh * 8 + j) * 512 + gidx] = lohi(acc2[j]);
}

// ---------------- kernel 3: lstm2 finish + attention (1 CTA per b, 512 thr) ----------------
__global__ __launch_bounds__(512) void k_attn(
    const float* __restrict__ key, const float* __restrict__ val,
    const int* __restrict__ elen,
    const float* __restrict__ bi2, const float* __restrict__ bh2,
    float* __restrict__ out, int t)
{
    const int b = blockIdx.x, tid = threadIdx.x;
    const int lane = tid & 31, warp = tid >> 5;
    __shared__ __align__(16) float q[128];
    __shared__ float gates[512];
    __shared__ float a[T_];
    __shared__ float red[32];
    __shared__ float cred[3 * 128];

    // ---- lstm2 finish: reduce 4 partials + biases, pointwise ----
    {
        float gsum = g_g2p[0 * (B * 512) + b * 512 + tid]
                   + g_g2p[1 * (B * 512) + b * 512 + tid]
                   + g_g2p[2 * (B * 512) + b * 512 + tid]
                   + g_g2p[3 * (B * 512) + b * 512 + tid];
        gates[tid] = gsum + bi2[tid] + bh2[tid];
    }
    __syncthreads();
    if (tid < 128) {
        float gi = gates[tid], gf = gates[128 + tid];
        float gg = gates[256 + tid], go = gates[384 + tid];
        int idx = b * KV + tid;
        float co = g_c2[idx];
        float cn = sigm(gf) * co + sigm(gi) * tanhf(gg);
        g_c2[idx] = cn;
        float h = sigm(go) * tanhf(cn);
        g_h2x[t & 1][idx] = h;
        q[tid] = h;
    }
    __syncthreads();

    const int len = elen[b];

    // ---- energies: 4 threads per row, FFMA2, uniform shuffles ----
    const int j4 = tid & 3, rb = tid >> 2;
#pragma unroll
    for (int rr = 0; rr < 4; rr++) {
        int row = rb + rr * 128;
        int rowc = (row < T_) ? row : (T_ - 1);
        const ulonglong2* kr = (const ulonglong2*)(key + ((size_t)b * T_ + rowc) * KV);
        const ulonglong2* qv = (const ulonglong2*)q;
        u64 t2 = 0ull;
#pragma unroll
        for (int i = 0; i < 8; i++) {
            ulonglong2 kk = kr[j4 + 4 * i];
            ulonglong2 qq = qv[j4 + 4 * i];
            ffma2(t2, kk.x, qq.x);
            ffma2(t2, kk.y, qq.y);
        }
        float s = lohi(t2);
        s += __shfl_xor_sync(0xffffffffu, s, 1);
        s += __shfl_xor_sync(0xffffffffu, s, 2);
        if (j4 == 0 && row < T_) a[row] = (row < len) ? s : NEG;
    }
    __syncthreads();

    // ---- max reduce ----
    float m = (tid < T_) ? a[tid] : -3.4e38f;
#pragma unroll
    for (int o = 16; o; o >>= 1) m = fmaxf(m, __shfl_xor_sync(0xffffffffu, m, o));
    if (lane == 0) red[warp] = m;
    __syncthreads();
    if (warp == 0) {
        float v = (lane < 16) ? red[lane] : -3.4e38f;
#pragma unroll
        for (int o = 16; o; o >>= 1) v = fmaxf(v, __shfl_xor_sync(0xffffffffu, v, o));
        if (lane == 0) red[0] = v;
    }
    __syncthreads();
    m = red[0];
    __syncthreads();

    // ---- exp + sum reduce ----
    float p = 0.f;
    if (tid < T_) { p = expf(a[tid] - m); a[tid] = p; }
    float s = p;
#pragma unroll
    for (int o = 16; o; o >>= 1) s += __shfl_xor_sync(0xffffffffu, s, o);
    if (lane == 0) red[warp] = s;
    __syncthreads();
    if (warp == 0) {
        float v = (lane < 16) ? red[lane] : 0.f;
#pragma unroll
        for (int o = 16; o; o >>= 1) v += __shfl_xor_sync(0xffffffffu, v, o);
        if (lane == 0) red[0] = v;
    }
    __syncthreads();
    const float inv = 1.0f / red[0];
    if (tid < T_) {
        float pn = a[tid] * inv;
        a[tid] = pn;
        if (b == 0) __stcs(out + (size_t)B * L_ * V_ + (size_t)t * T_ + tid, pn);
    }
    __syncthreads();

    // ---- context = attn @ value over 4 row-segments of 100 ----
    const int k = tid & 127, seg = tid >> 7;
    float acc = 0.f;
    const int t0 = seg * 100;
    int t1 = t0 + 100; if (t1 > len) t1 = len;
#pragma unroll 8
    for (int tt = t0; tt < t1; tt++)
        acc += a[tt] * val[((size_t)b * T_ + tt) * KV + k];
    if (seg) cred[(seg - 1) * 128 + k] = acc;
    __syncthreads();
    if (seg == 0)
        g_ctx[b * KV + k] = acc + cred[k] + cred[128 + k] + cred[256 + k];
}

// ---------------- final logits for step L-1 ----------------
__global__ __launch_bounds__(256) void k_logits_fin(
    const float* __restrict__ b_out, float* __restrict__ out)
{
    logits_part(blockIdx.x, b_out, out, L_);   // tout = L_-1, h2 = g_h2x[(L_+1)&1]
}

// ---------------- launch ----------------
extern "C" void kernel_launch(void* const* d_in, const int* in_sizes, int n_in,
                              void* d_out, int out_size)
{
    const float* enc_key  = (const float*)d_in[0];
    const float* enc_val  = (const float*)d_in[1];
    const int*   elen     = (const int*)  d_in[2];
    const int*   y        = (const int*)  d_in[3];
    const float* emb      = (const float*)d_in[4];
    const float* w_ih1    = (const float*)d_in[5];
    const float* w_hh1    = (const float*)d_in[6];
    const float* b_ih1    = (const float*)d_in[7];
    const float* b_hh1    = (const float*)d_in[8];
    const float* w_ih2    = (const float*)d_in[9];
    const float* w_hh2    = (const float*)d_in[10];
    const float* b_ih2    = (const float*)d_in[11];
    const float* b_hh2    = (const float*)d_in[12];
    const float* w_out    = (const float*)d_in[13];
    const float* b_out    = (const float*)d_in[14];
    float* out = (float*)d_out;

    k_init<<<256, 256>>>();
    k_prep<<<(N_WT1 + N_WT2 + N_WTO + 255) / 256, 256>>>(w_ih1, w_hh1, w_ih2, w_hh2, w_out);
    for (int t = 0; t < L_; t++) {
        k_step1<<<144, 256>>>(emb, y, b_ih1, b_hh1, b_out, out, t);
        k_lstm2p<<<128, 256>>>(t);
        k_attn <<<B, 512>>>(enc_key, enc_val, elen, b_ih2, b_hh2, out, t);
    }
    k_logits_fin<<<16, 256>>>(b_out, out);
}